// round 4
// baseline (speedup 1.0000x reference)
#include <cuda_runtime.h>
#include <math.h>

// Problem constants: B=1048576, M=8, K=3, R=8
#define M 8
#define Kc 3
#define R 8
#define CW 28           // coefficient row width per rule (floats), 16B aligned
#define ROWS_PER_PASS 32   // rows covered by one pass of a 256-thread block
#define PASSES 2           // rows per block = 64

__global__ __launch_bounds__(256)
void anfis_kernel(const float* __restrict__ x,
                  const float* __restrict__ c,
                  const float* __restrict__ log_sigma,
                  const float* __restrict__ cons,      // (R, M+1)
                  const int*   __restrict__ rules,     // (R, M)
                  float* __restrict__ out, int B)
{
    // Per-rule packed coefficients:
    //  [0..7]  a_m = -h ; [8..15] b_m = 2*h*c ; [16] k0 = -sum h*c^2
    //  [17] bias ; [18..25] w_m ; [26..27] pad
    __shared__ float s_coef[R * CW];

    const int tid = threadIdx.x;

    if (tid < R) {
        const int r = tid;
        float k0 = 0.f;
        #pragma unroll
        for (int m = 0; m < M; m++) {
            int k = rules[r * M + m];
            float sg = expf(log_sigma[m * Kc + k]) + 1e-6f;
            float h  = 0.5f / (sg * sg);
            float cc = c[m * Kc + k];
            s_coef[r * CW + m]      = -h;
            s_coef[r * CW + 8 + m]  = 2.f * h * cc;
            k0 -= h * cc * cc;
            s_coef[r * CW + 18 + m] = cons[r * (M + 1) + 1 + m];
        }
        s_coef[r * CW + 16] = k0;
        s_coef[r * CW + 17] = cons[r * (M + 1)];
        s_coef[r * CW + 26] = 0.f;
        s_coef[r * CW + 27] = 0.f;
    }
    __syncthreads();

    const int rule = tid & 7;        // lane's rule
    const int rslot = tid >> 3;      // row slot 0..31 within a pass

    // Load this lane's rule coefficients once (7 LDS.128, bank-conflict-free)
    const float4* S4 = (const float4*)(s_coef + rule * CW);
    const float4 A0 = S4[0];   // a0..a3
    const float4 A1 = S4[1];   // a4..a7
    const float4 B0 = S4[2];   // b0..b3
    const float4 B1 = S4[3];   // b4..b7
    const float4 C0 = S4[4];   // k0, bias, w0, w1
    const float4 C1 = S4[5];   // w2..w5
    const float4 C2 = S4[6];   // w6, w7, pad, pad

    const int base_row = blockIdx.x * (ROWS_PER_PASS * PASSES);

    #pragma unroll
    for (int it = 0; it < PASSES; it++) {
        const int row = base_row + it * ROWS_PER_PASS + rslot;
        if (row >= B) break;

        // x row: 32B (8 lanes of a group hit identical sectors -> coalesced)
        const float4* xp = (const float4*)(x + (size_t)row * M);
        const float4 xa = xp[0];
        const float4 xb = xp[1];

        // firing exponent: e = k0 + sum_m (a_m*x + b_m)*x   (independent t_m, 8-fma chain)
        float e = C0.x;
        e = fmaf(fmaf(A0.x, xa.x, B0.x), xa.x, e);
        e = fmaf(fmaf(A0.y, xa.y, B0.y), xa.y, e);
        e = fmaf(fmaf(A0.z, xa.z, B0.z), xa.z, e);
        e = fmaf(fmaf(A0.w, xa.w, B0.w), xa.w, e);
        e = fmaf(fmaf(A1.x, xb.x, B1.x), xb.x, e);
        e = fmaf(fmaf(A1.y, xb.y, B1.y), xb.y, e);
        e = fmaf(fmaf(A1.z, xb.z, B1.z), xb.z, e);
        e = fmaf(fmaf(A1.w, xb.w, B1.w), xb.w, e);
        const float f = __expf(e);

        // consequent: yr = bias + x . w
        float yr = fmaf(C0.z, xa.x, C0.y);
        yr = fmaf(C0.w, xa.y, yr);
        yr = fmaf(C1.x, xa.z, yr);
        yr = fmaf(C1.y, xa.w, yr);
        yr = fmaf(C1.z, xb.x, yr);
        yr = fmaf(C1.w, xb.y, yr);
        yr = fmaf(C2.x, xb.z, yr);
        yr = fmaf(C2.y, xb.w, yr);

        // fsum over the 8-lane rule group (butterfly)
        float fs = f;
        fs += __shfl_xor_sync(0xffffffffu, fs, 1);
        fs += __shfl_xor_sync(0xffffffffu, fs, 2);
        fs += __shfl_xor_sync(0xffffffffu, fs, 4);

        const float inv = __fdividef(1.0f, fs + 1e-8f);
        const float wn = f * inv;

        // outputs: w_norm and y_r are linear in tid -> fully coalesced STG.32
        const size_t o = (size_t)(base_row + it * ROWS_PER_PASS) * R + tid;
        out[(size_t)B + o]     = wn;
        out[(size_t)B * 9 + o] = yr;

        // y = sum_r wn*yr (butterfly), lane rule==0 stores
        float p = wn * yr;
        p += __shfl_xor_sync(0xffffffffu, p, 1);
        p += __shfl_xor_sync(0xffffffffu, p, 2);
        p += __shfl_xor_sync(0xffffffffu, p, 4);
        if (rule == 0) out[row] = p;
    }
}

extern "C" void kernel_launch(void* const* d_in, const int* in_sizes, int n_in,
                              void* d_out, int out_size)
{
    const float* x         = (const float*)d_in[0];
    const float* c         = (const float*)d_in[1];
    const float* log_sigma = (const float*)d_in[2];
    const float* cons      = (const float*)d_in[3];
    const int*   rules     = (const int*)d_in[4];
    float* out = (float*)d_out;

    const int B = in_sizes[0] / M;   // 1048576
    const int rows_per_block = ROWS_PER_PASS * PASSES;  // 64
    const int blocks = (B + rows_per_block - 1) / rows_per_block;
    anfis_kernel<<<blocks, 256>>>(x, c, log_sigma, cons, rules, out, B);
}

// round 5
// speedup vs baseline: 2.1241x; 2.1241x over previous
#include <cuda_runtime.h>
#include <math.h>

// Problem constants: B=1048576, M=8, K=3, R=8
#define M 8
#define Kc 3
#define R 8
#define NPAIR 4          // rule pairs
#define PW 56            // floats per pair row (26 packed entries *2 floats, padded to 56 -> 14x16B)

typedef unsigned long long u64;

static __device__ __forceinline__ u64 pk2(float lo, float hi) {
    u64 r; asm("mov.b64 %0, {%1,%2};" : "=l"(r) : "f"(lo), "f"(hi)); return r;
}
static __device__ __forceinline__ void upk2(u64 v, float& lo, float& hi) {
    asm("mov.b64 {%0,%1}, %2;" : "=f"(lo), "=f"(hi) : "l"(v));
}
static __device__ __forceinline__ u64 fma2(u64 a, u64 b, u64 c) {
    u64 d; asm("fma.rn.f32x2 %0, %1, %2, %3;" : "=l"(d) : "l"(a), "l"(b), "l"(c)); return d;
}

__global__ __launch_bounds__(256)
void anfis_kernel(const float* __restrict__ x,
                  const float* __restrict__ c,
                  const float* __restrict__ log_sigma,
                  const float* __restrict__ cons,      // (R, M+1)
                  const int*   __restrict__ rules,     // (R, M)
                  float* __restrict__ out, int B)
{
    // Scalar scratch for per-rule coefficients, then packed pair layout.
    // Packed entry j (float2) for pair p: rules (2p, 2p+1)
    //   j=0..7  : a_m = -h
    //   j=8..15 : b_m = 2*h*c
    //   j=16    : k0  = -sum h*c^2
    //   j=17    : bias
    //   j=18..25: w_m
    __shared__ float s_raw[R][26];
    __shared__ __align__(16) float s_pack[NPAIR * PW];

    const int tid = threadIdx.x;

    if (tid < R) {
        const int r = tid;
        float k0 = 0.f;
        #pragma unroll
        for (int m = 0; m < M; m++) {
            int k = rules[r * M + m];
            float sg = expf(log_sigma[m * Kc + k]) + 1e-6f;
            float h  = 0.5f / (sg * sg);
            float cc = c[m * Kc + k];
            s_raw[r][m]      = -h;
            s_raw[r][8 + m]  = 2.f * h * cc;
            k0 -= h * cc * cc;
            s_raw[r][18 + m] = cons[r * (M + 1) + 1 + m];
        }
        s_raw[r][16] = k0;
        s_raw[r][17] = cons[r * (M + 1)];
    }
    __syncthreads();
    if (tid < NPAIR * 26) {
        const int p = tid / 26, j = tid % 26;
        s_pack[p * PW + 2 * j]     = s_raw[2 * p][j];
        s_pack[p * PW + 2 * j + 1] = s_raw[2 * p + 1][j];
    }
    if (tid >= NPAIR * 26 && tid < NPAIR * 28) {   // zero the pad
        const int p = (tid - NPAIR * 26) / 2;
        s_pack[p * PW + 52 + (tid & 1)] = 0.f;
        s_pack[p * PW + 54 + (tid & 1)] = 0.f;
    }
    __syncthreads();

    const int b = blockIdx.x * blockDim.x + tid;
    if (b >= B) return;

    // ---- load x row: 32 contiguous bytes ----
    const float4 xa = *(const float4*)(x + (size_t)b * M);
    const float4 xb = *(const float4*)(x + (size_t)b * M + 4);
    const float xv[M] = {xa.x, xa.y, xa.z, xa.w, xb.x, xb.y, xb.z, xb.w};

    // pack x_m into both lanes once per row
    u64 px[M];
    #pragma unroll
    for (int m = 0; m < M; m++) px[m] = pk2(xv[m], xv[m]);

    float f[R], yr[R];
    float fsum = 0.f;

    #pragma unroll
    for (int p = 0; p < NPAIR; p++) {
        const u64* S = (const u64*)(s_pack + p * PW);  // 26 packed entries

        // exponent: e = k0 + sum_m ((a_m*x + b_m) * x)   (packed over rule pair)
        u64 e = S[16];
        #pragma unroll
        for (int m = 0; m < M; m++)
            e = fma2(fma2(S[m], px[m], S[8 + m]), px[m], e);

        // consequent: t = bias + sum_m w_m * x
        u64 t = S[17];
        #pragma unroll
        for (int m = 0; m < M; m++)
            t = fma2(S[18 + m], px[m], t);

        float e0, e1;
        upk2(e, e0, e1);
        const float f0 = __expf(e0);
        const float f1 = __expf(e1);
        f[2 * p] = f0;
        f[2 * p + 1] = f1;
        fsum += f0 + f1;
        upk2(t, yr[2 * p], yr[2 * p + 1]);
    }

    const float inv = __fdividef(1.0f, fsum + 1e-8f);

    float wn[R];
    float y = 0.f;
    #pragma unroll
    for (int r = 0; r < R; r++) {
        wn[r] = f[r] * inv;
        y = fmaf(wn[r], yr[r], y);
    }

    // ---- outputs: flat concat  y[0,B) | w_norm[B,9B) | y_r[9B,17B) ----
    out[b] = y;

    float4* wo = (float4*)(out + (size_t)B + (size_t)b * R);
    wo[0] = make_float4(wn[0], wn[1], wn[2], wn[3]);
    wo[1] = make_float4(wn[4], wn[5], wn[6], wn[7]);

    float4* yo = (float4*)(out + (size_t)B * 9 + (size_t)b * R);
    yo[0] = make_float4(yr[0], yr[1], yr[2], yr[3]);
    yo[1] = make_float4(yr[4], yr[5], yr[6], yr[7]);
}

extern "C" void kernel_launch(void* const* d_in, const int* in_sizes, int n_in,
                              void* d_out, int out_size)
{
    const float* x         = (const float*)d_in[0];
    const float* c         = (const float*)d_in[1];
    const float* log_sigma = (const float*)d_in[2];
    const float* cons      = (const float*)d_in[3];
    const int*   rules     = (const int*)d_in[4];
    float* out = (float*)d_out;

    const int B = in_sizes[0] / M;   // 1048576
    const int threads = 256;
    const int blocks = (B + threads - 1) / threads;
    anfis_kernel<<<blocks, threads>>>(x, c, log_sigma, cons, rules, out, B);
}

// round 6
// speedup vs baseline: 2.4451x; 1.1511x over previous
#include <cuda_runtime.h>
#include <math.h>

// Problem constants: B=1048576, M=8, K=3, R=8
#define M 8
#define Kc 3
#define R 8
#define NPAIR 4          // rule pairs (f32x2 lanes = 2 rules)
#define PW 56            // floats per pair row (26 packed entries*2, padded; 16B aligned)

typedef unsigned long long u64;

static __device__ __forceinline__ u64 pk2(float lo, float hi) {
    u64 r; asm("mov.b64 %0, {%1,%2};" : "=l"(r) : "f"(lo), "f"(hi)); return r;
}
static __device__ __forceinline__ void upk2(u64 v, float& lo, float& hi) {
    asm("mov.b64 {%0,%1}, %2;" : "=f"(lo), "=f"(hi) : "l"(v));
}
static __device__ __forceinline__ u64 fma2(u64 a, u64 b, u64 c) {
    u64 d; asm("fma.rn.f32x2 %0, %1, %2, %3;" : "=l"(d) : "l"(a), "l"(b), "l"(c)); return d;
}

__global__ __launch_bounds__(256)
void anfis_kernel(const float* __restrict__ x,
                  const float* __restrict__ c,
                  const float* __restrict__ log_sigma,
                  const float* __restrict__ cons,      // (R, M+1)
                  const int*   __restrict__ rules,     // (R, M)
                  float* __restrict__ out, int B)
{
    // Packed entry j (float2 over rule pair p = rules 2p,2p+1):
    //  j=0..7: a_m=-h ; j=8..15: b_m=2hc ; j=16: k0=-sum h c^2 ; j=17: bias ; j=18..25: w_m
    __shared__ float s_raw[R][26];
    __shared__ __align__(16) float s_pack[NPAIR * PW];

    const int tid = threadIdx.x;

    if (tid < R) {
        const int r = tid;
        float k0 = 0.f;
        #pragma unroll
        for (int m = 0; m < M; m++) {
            int k = rules[r * M + m];
            float sg = expf(log_sigma[m * Kc + k]) + 1e-6f;
            float h  = 0.5f / (sg * sg);
            float cc = c[m * Kc + k];
            s_raw[r][m]      = -h;
            s_raw[r][8 + m]  = 2.f * h * cc;
            k0 -= h * cc * cc;
            s_raw[r][18 + m] = cons[r * (M + 1) + 1 + m];
        }
        s_raw[r][16] = k0;
        s_raw[r][17] = cons[r * (M + 1)];
    }
    __syncthreads();
    if (tid < NPAIR * 28) {
        const int p = tid / 28, j = tid % 28;
        float v0 = (j < 26) ? s_raw[2 * p][j]     : 0.f;
        float v1 = (j < 26) ? s_raw[2 * p + 1][j] : 0.f;
        s_pack[p * PW + 2 * j]     = v0;
        s_pack[p * PW + 2 * j + 1] = v1;
    }
    __syncthreads();

    // two rows per thread, stride blockDim for coalescing
    const int b0 = blockIdx.x * (blockDim.x * 2) + tid;
    const int b1 = b0 + blockDim.x;
    if (b1 >= B) {
        // tail guard (never taken for B=1M with 2048 blocks, kept for safety)
        if (b0 >= B) return;
    }

    // ---- load both x rows (32B each, coalesced) ----
    const float4 xa0 = *(const float4*)(x + (size_t)b0 * M);
    const float4 xb0 = *(const float4*)(x + (size_t)b0 * M + 4);
    const float4 xa1 = *(const float4*)(x + (size_t)b1 * M);
    const float4 xb1 = *(const float4*)(x + (size_t)b1 * M + 4);

    u64 p0[M], p1[M];
    p0[0]=pk2(xa0.x,xa0.x); p0[1]=pk2(xa0.y,xa0.y); p0[2]=pk2(xa0.z,xa0.z); p0[3]=pk2(xa0.w,xa0.w);
    p0[4]=pk2(xb0.x,xb0.x); p0[5]=pk2(xb0.y,xb0.y); p0[6]=pk2(xb0.z,xb0.z); p0[7]=pk2(xb0.w,xb0.w);
    p1[0]=pk2(xa1.x,xa1.x); p1[1]=pk2(xa1.y,xa1.y); p1[2]=pk2(xa1.z,xa1.z); p1[3]=pk2(xa1.w,xa1.w);
    p1[4]=pk2(xb1.x,xb1.x); p1[5]=pk2(xb1.y,xb1.y); p1[6]=pk2(xb1.z,xb1.z); p1[7]=pk2(xb1.w,xb1.w);

    float f0[R], f1[R], yr0[R], yr1[R];
    float fs0 = 0.f, fs1 = 0.f;

    #pragma unroll
    for (int p = 0; p < NPAIR; p++) {
        const u64* S = (const u64*)(s_pack + p * PW);  // 26 packed entries (LDS.128-mergeable)

        u64 e0 = S[16], e1 = S[16];
        u64 t0 = S[17], t1 = S[17];
        #pragma unroll
        for (int m = 0; m < M; m++) {
            const u64 A = S[m], Bc = S[8 + m], W = S[18 + m];
            e0 = fma2(fma2(A, p0[m], Bc), p0[m], e0);
            e1 = fma2(fma2(A, p1[m], Bc), p1[m], e1);
            t0 = fma2(W, p0[m], t0);
            t1 = fma2(W, p1[m], t1);
        }

        float ea, eb;
        upk2(e0, ea, eb);
        float fa = __expf(ea), fb = __expf(eb);
        f0[2*p] = fa; f0[2*p+1] = fb; fs0 += fa + fb;
        upk2(e1, ea, eb);
        fa = __expf(ea); fb = __expf(eb);
        f1[2*p] = fa; f1[2*p+1] = fb; fs1 += fa + fb;

        upk2(t0, yr0[2*p], yr0[2*p+1]);
        upk2(t1, yr1[2*p], yr1[2*p+1]);
    }

    // ---- store y_r immediately (no normalization needed) ----
    float4* yo0 = (float4*)(out + (size_t)B * 9 + (size_t)b0 * R);
    yo0[0] = make_float4(yr0[0], yr0[1], yr0[2], yr0[3]);
    yo0[1] = make_float4(yr0[4], yr0[5], yr0[6], yr0[7]);
    float4* yo1 = (float4*)(out + (size_t)B * 9 + (size_t)b1 * R);
    yo1[0] = make_float4(yr1[0], yr1[1], yr1[2], yr1[3]);
    yo1[1] = make_float4(yr1[4], yr1[5], yr1[6], yr1[7]);

    const float inv0 = __fdividef(1.0f, fs0 + 1e-8f);
    const float inv1 = __fdividef(1.0f, fs1 + 1e-8f);

    float wn0[R], wn1[R];
    float y0 = 0.f, y1 = 0.f;
    #pragma unroll
    for (int r = 0; r < R; r++) {
        wn0[r] = f0[r] * inv0;
        wn1[r] = f1[r] * inv1;
        y0 = fmaf(wn0[r], yr0[r], y0);
        y1 = fmaf(wn1[r], yr1[r], y1);
    }

    out[b0] = y0;
    out[b1] = y1;

    float4* wo0 = (float4*)(out + (size_t)B + (size_t)b0 * R);
    wo0[0] = make_float4(wn0[0], wn0[1], wn0[2], wn0[3]);
    wo0[1] = make_float4(wn0[4], wn0[5], wn0[6], wn0[7]);
    float4* wo1 = (float4*)(out + (size_t)B + (size_t)b1 * R);
    wo1[0] = make_float4(wn1[0], wn1[1], wn1[2], wn1[3]);
    wo1[1] = make_float4(wn1[4], wn1[5], wn1[6], wn1[7]);
}

extern "C" void kernel_launch(void* const* d_in, const int* in_sizes, int n_in,
                              void* d_out, int out_size)
{
    const float* x         = (const float*)d_in[0];
    const float* c         = (const float*)d_in[1];
    const float* log_sigma = (const float*)d_in[2];
    const float* cons      = (const float*)d_in[3];
    const int*   rules     = (const int*)d_in[4];
    float* out = (float*)d_out;

    const int B = in_sizes[0] / M;            // 1048576
    const int threads = 256;
    const int rows_per_block = threads * 2;   // 512
    const int blocks = (B + rows_per_block - 1) / rows_per_block;
    anfis_kernel<<<blocks, threads>>>(x, c, log_sigma, cons, rules, out, B);
}